// round 8
// baseline (speedup 1.0000x reference)
#include <cuda_runtime.h>
#include <math.h>

// Problem constants
#define BSZ  2
#define LSEQ 2048
#define EMB  1024
#define HN   16
#define DHD  64
#define DFF  4096
#define MR   (BSZ*LSEQ)     // 4096 rows
#define N3E  (3*EMB)        // 3072

// ---------------------------------------------------------------------------
// Scratch (device globals; no allocation in kernel_launch)
// ---------------------------------------------------------------------------
__device__ float g_wqkv[(size_t)EMB * N3E];       // packed QKV weights (E x 3072)
__device__ float g_bqkv[N3E];                     // packed QKV bias
__device__ float g_qkv[(size_t)MR * N3E];         // q|k|v, row = token, col = proj*1024+h*64+d
__device__ float g_z  [(size_t)MR * EMB];         // attention output (concat heads)
__device__ float g_t1 [(size_t)MR * EMB];         // pre-LN residual buffer (reused)
__device__ float g_h  [(size_t)MR * EMB];         // post-LN1 hidden
__device__ float g_ff [(size_t)MR * DFF];         // FFN intermediate

// ---------------------------------------------------------------------------
// Pack Wq/Wk/Wv (H,E,Dh) -> Wqkv (E, 3*E) row-major; biases (H,Dh) -> (3*E)
// ---------------------------------------------------------------------------
__global__ void pack_qkv_kernel(const float* __restrict__ Wq, const float* __restrict__ Wk,
                                const float* __restrict__ Wv, const float* __restrict__ bq,
                                const float* __restrict__ bk, const float* __restrict__ bv)
{
    int idx = blockIdx.x * blockDim.x + threadIdx.x;
    const int total = EMB * N3E;
    if (idx < total) {
        int n = idx % N3E;
        int e = idx / N3E;
        int proj = n / EMB;
        int hd   = n % EMB;              // h*64 + d
        const float* W = (proj == 0) ? Wq : (proj == 1) ? Wk : Wv;
        // W[h][e][d] at h*E*Dh + e*Dh + d
        g_wqkv[idx] = W[(size_t)(hd >> 6) * EMB * DHD + (size_t)e * DHD + (hd & 63)];
    }
    if (idx < N3E) {
        int proj = idx / EMB;
        int hd   = idx % EMB;
        const float* bb = (proj == 0) ? bq : (proj == 1) ? bk : bv;
        g_bqkv[idx] = bb[hd];
    }
}

// ---------------------------------------------------------------------------
// SGEMM: C(MxN) = A(MxK) @ B(KxN) + bias[n] (+ res[m][n]) (relu optional)
// 128x128 tile, BK=8, 256 threads, 8x8 per thread, double-buffered smem.
// M,N multiples of 128; K multiple of 8.
// ---------------------------------------------------------------------------
template<bool RELU, bool ADDRES>
__global__ __launch_bounds__(256, 2)
void sgemm128(const float* __restrict__ A, const float* __restrict__ B,
              const float* __restrict__ bias, const float* __restrict__ res,
              float* __restrict__ C, int M, int N, int K)
{
    __shared__ float As[2][8][128];
    __shared__ float Bs[2][8][128];

    const int tid = threadIdx.x;
    const int bx = blockIdx.x, by = blockIdx.y;

    // global load indices
    const int arow = tid >> 1;             // 0..127
    const int acol = (tid & 1) << 2;       // 0 or 4
    const int brow = tid >> 5;             // 0..7
    const int bcol = (tid & 31) << 2;      // 0..124

    const float* Ag = A + (size_t)(by * 128 + arow) * K + acol;
    const float* Bg = B + (size_t)brow * N + bx * 128 + bcol;

    // prologue: load tile 0
    {
        float4 av = *(const float4*)Ag;
        As[0][acol + 0][arow] = av.x;
        As[0][acol + 1][arow] = av.y;
        As[0][acol + 2][arow] = av.z;
        As[0][acol + 3][arow] = av.w;
        float4 bv = *(const float4*)Bg;
        *(float4*)&Bs[0][brow][bcol] = bv;
    }
    __syncthreads();

    float acc[8][8];
#pragma unroll
    for (int i = 0; i < 8; ++i)
#pragma unroll
        for (int j = 0; j < 8; ++j) acc[i][j] = 0.f;

    const int tx = tid & 15;   // col group
    const int ty = tid >> 4;   // row group
    int buf = 0;

    for (int kt = 0; kt < K; kt += 8) {
        float4 av, bv;
        const bool more = (kt + 8) < K;
        if (more) {
            av = *(const float4*)(Ag + (kt + 8));
            bv = *(const float4*)(Bg + (size_t)(kt + 8) * N);
        }

        const float (*Asb)[128] = As[buf];
        const float (*Bsb)[128] = Bs[buf];
#pragma unroll
        for (int k = 0; k < 8; ++k) {
            float4 a0 = *(const float4*)&Asb[k][ty * 4];
            float4 a1 = *(const float4*)&Asb[k][64 + ty * 4];
            float4 b0 = *(const float4*)&Bsb[k][tx * 4];
            float4 b1 = *(const float4*)&Bsb[k][64 + tx * 4];
            float af[8] = {a0.x, a0.y, a0.z, a0.w, a1.x, a1.y, a1.z, a1.w};
            float bf[8] = {b0.x, b0.y, b0.z, b0.w, b1.x, b1.y, b1.z, b1.w};
#pragma unroll
            for (int i = 0; i < 8; ++i)
#pragma unroll
                for (int j = 0; j < 8; ++j) acc[i][j] += af[i] * bf[j];
        }

        if (more) {
            int nb = buf ^ 1;
            As[nb][acol + 0][arow] = av.x;
            As[nb][acol + 1][arow] = av.y;
            As[nb][acol + 2][arow] = av.z;
            As[nb][acol + 3][arow] = av.w;
            *(float4*)&Bs[nb][brow][bcol] = bv;
            __syncthreads();
            buf = nb;
        }
    }

    // epilogue
#pragma unroll
    for (int i = 0; i < 8; ++i) {
        int m = by * 128 + ((i < 4) ? (ty * 4 + i) : (64 + ty * 4 + i - 4));
#pragma unroll
        for (int jg = 0; jg < 2; ++jg) {
            int n = bx * 128 + jg * 64 + tx * 4;
            float4 v = make_float4(acc[i][jg * 4 + 0], acc[i][jg * 4 + 1],
                                   acc[i][jg * 4 + 2], acc[i][jg * 4 + 3]);
            float4 bi = *(const float4*)&bias[n];
            v.x += bi.x; v.y += bi.y; v.z += bi.z; v.w += bi.w;
            if (ADDRES) {
                float4 r = *(const float4*)&res[(size_t)m * N + n];
                v.x += r.x; v.y += r.y; v.z += r.z; v.w += r.w;
            }
            if (RELU) {
                v.x = fmaxf(v.x, 0.f); v.y = fmaxf(v.y, 0.f);
                v.z = fmaxf(v.z, 0.f); v.w = fmaxf(v.w, 0.f);
            }
            *(float4*)&C[(size_t)m * N + n] = v;
        }
    }
}

// ---------------------------------------------------------------------------
// LayerNorm: one block per row of 1024, eps=1e-5, out = (x-m)/sqrt(v+eps)*g + b
// ---------------------------------------------------------------------------
__device__ __forceinline__ float block_sum_1024(float v, float* red)
{
#pragma unroll
    for (int o = 16; o; o >>= 1) v += __shfl_xor_sync(0xffffffffu, v, o);
    int w = threadIdx.x >> 5;
    if ((threadIdx.x & 31) == 0) red[w] = v;
    __syncthreads();
    if (threadIdx.x < 32) {
        float t = (threadIdx.x < 8) ? red[threadIdx.x] : 0.f;
#pragma unroll
        for (int o = 4; o; o >>= 1) t += __shfl_xor_sync(0xffffffffu, t, o);
        if (threadIdx.x == 0) red[0] = t;
    }
    __syncthreads();
    float r = red[0];
    __syncthreads();
    return r;
}

__global__ __launch_bounds__(256)
void layernorm_kernel(const float* __restrict__ in, const float* __restrict__ g,
                      const float* __restrict__ beta, float* __restrict__ out)
{
    __shared__ float red[8];
    const int row = blockIdx.x;
    const int tid = threadIdx.x;
    float4 v = ((const float4*)(in + (size_t)row * EMB))[tid];
    float s = v.x + v.y + v.z + v.w;
    float mean = block_sum_1024(s, red) * (1.f / EMB);
    float dx = v.x - mean, dy = v.y - mean, dz = v.z - mean, dw = v.w - mean;
    float sq = dx * dx + dy * dy + dz * dz + dw * dw;
    float var = block_sum_1024(sq, red) * (1.f / EMB);
    float rstd = rsqrtf(var + 1e-5f);
    float4 gv = ((const float4*)g)[tid];
    float4 bv = ((const float4*)beta)[tid];
    float4 o;
    o.x = dx * rstd * gv.x + bv.x;
    o.y = dy * rstd * gv.y + bv.y;
    o.z = dz * rstd * gv.z + bv.z;
    o.w = dw * rstd * gv.w + bv.w;
    ((float4*)(out + (size_t)row * EMB))[tid] = o;
}

// ---------------------------------------------------------------------------
// Causal flash attention, fp32. One CTA per (qblock of 64, head, batch).
// qkv layout: row (b*L + l), cols [0,1024)=q, [1024,2048)=k, [2048,3072)=v,
// within each: h*64 + d. z out: row (b*L+l), col h*64 + d (concat-heads).
// ---------------------------------------------------------------------------
struct AttnSmem {
    float Qs[64][68];
    float Ks[64][68];
    float Vs[64][68];
    float Ss[64][68];
    float Pt[64][68];   // transposed probabilities: Pt[j][i]
    float mrow[64];
    float lrow[64];
    float arow[64];
};

#define DOT4(a, b) ((a).x*(b).x + (a).y*(b).y + (a).z*(b).z + (a).w*(b).w)

__global__ __launch_bounds__(256, 1)
void attn_kernel(const float* __restrict__ qkv, float* __restrict__ z)
{
    extern __shared__ char smem_raw[];
    AttnSmem& sm = *reinterpret_cast<AttnSmem*>(smem_raw);

    const int qb = blockIdx.x;        // 0..31
    const int h  = blockIdx.y;        // 0..15
    const int b  = blockIdx.z;        // 0..1
    const int tid = threadIdx.x;      // 256
    const int tx = tid & 15, ty = tid >> 4;
    const size_t rs = N3E;
    const float scale = 0.125f;       // 1/sqrt(64)

    // load Q tile (pre-scaled)
    const float* qbase = qkv + (size_t)(b * LSEQ + qb * 64) * rs + h * 64;
#pragma unroll
    for (int it = 0; it < 4; ++it) {
        int idx = tid + it * 256;              // 0..1023
        int r = idx >> 4, c4 = (idx & 15) << 2;
        float4 v = *(const float4*)(qbase + (size_t)r * rs + c4);
        sm.Qs[r][c4 + 0] = v.x * scale;
        sm.Qs[r][c4 + 1] = v.y * scale;
        sm.Qs[r][c4 + 2] = v.z * scale;
        sm.Qs[r][c4 + 3] = v.w * scale;
    }
    if (tid < 64) { sm.mrow[tid] = -1e30f; sm.lrow[tid] = 0.f; }

    float acc[4][4];
#pragma unroll
    for (int i = 0; i < 4; ++i)
#pragma unroll
        for (int j = 0; j < 4; ++j) acc[i][j] = 0.f;

    for (int kb = 0; kb <= qb; ++kb) {
        __syncthreads();  // previous PV done reading Pt/Vs; Q stores visible on first iter

        const float* kbase = qkv + (size_t)(b * LSEQ + kb * 64) * rs + EMB + h * 64;
        const float* vbase = kbase + EMB;
#pragma unroll
        for (int it = 0; it < 4; ++it) {
            int idx = tid + it * 256;
            int r = idx >> 4, c4 = (idx & 15) << 2;
            float4 kv = *(const float4*)(kbase + (size_t)r * rs + c4);
            sm.Ks[r][c4 + 0] = kv.x; sm.Ks[r][c4 + 1] = kv.y;
            sm.Ks[r][c4 + 2] = kv.z; sm.Ks[r][c4 + 3] = kv.w;
            float4 vv = *(const float4*)(vbase + (size_t)r * rs + c4);
            sm.Vs[r][c4 + 0] = vv.x; sm.Vs[r][c4 + 1] = vv.y;
            sm.Vs[r][c4 + 2] = vv.z; sm.Vs[r][c4 + 3] = vv.w;
        }
        __syncthreads();

        // S = (Q*scale) @ K^T  (rows i = ty+16*ii, cols j = tx+16*jj)
        float s[4][4];
#pragma unroll
        for (int i = 0; i < 4; ++i)
#pragma unroll
            for (int j = 0; j < 4; ++j) s[i][j] = 0.f;
#pragma unroll
        for (int d4 = 0; d4 < 64; d4 += 4) {
            float4 q0 = *(const float4*)&sm.Qs[ty     ][d4];
            float4 q1 = *(const float4*)&sm.Qs[ty + 16][d4];
            float4 q2 = *(const float4*)&sm.Qs[ty + 32][d4];
            float4 q3 = *(const float4*)&sm.Qs[ty + 48][d4];
            float4 k0 = *(const float4*)&sm.Ks[tx     ][d4];
            float4 k1 = *(const float4*)&sm.Ks[tx + 16][d4];
            float4 k2 = *(const float4*)&sm.Ks[tx + 32][d4];
            float4 k3 = *(const float4*)&sm.Ks[tx + 48][d4];
            s[0][0] += DOT4(q0,k0); s[0][1] += DOT4(q0,k1); s[0][2] += DOT4(q0,k2); s[0][3] += DOT4(q0,k3);
            s[1][0] += DOT4(q1,k0); s[1][1] += DOT4(q1,k1); s[1][2] += DOT4(q1,k2); s[1][3] += DOT4(q1,k3);
            s[2][0] += DOT4(q2,k0); s[2][1] += DOT4(q2,k1); s[2][2] += DOT4(q2,k2); s[2][3] += DOT4(q2,k3);
            s[3][0] += DOT4(q3,k0); s[3][1] += DOT4(q3,k1); s[3][2] += DOT4(q3,k2); s[3][3] += DOT4(q3,k3);
        }
#pragma unroll
        for (int ii = 0; ii < 4; ++ii)
#pragma unroll
            for (int jj = 0; jj < 4; ++jj)
                sm.Ss[ty + 16 * ii][tx + 16 * jj] = s[ii][jj];
        __syncthreads();

        // online softmax per row (threads 0..63)
        if (tid < 64) {
            const int r = tid;
            const bool diag = (kb == qb);
            float m_old = sm.mrow[r];
            float mmax = m_old;
#pragma unroll
            for (int j4 = 0; j4 < 64; j4 += 4) {
                float4 v = *(const float4*)&sm.Ss[r][j4];
                if (diag) {
                    if (j4 + 0 > r) v.x = -1e30f;
                    if (j4 + 1 > r) v.y = -1e30f;
                    if (j4 + 2 > r) v.z = -1e30f;
                    if (j4 + 3 > r) v.w = -1e30f;
                }
                mmax = fmaxf(mmax, fmaxf(fmaxf(v.x, v.y), fmaxf(v.z, v.w)));
            }
            float alpha = expf(m_old - mmax);
            float lsum = 0.f;
#pragma unroll
            for (int j4 = 0; j4 < 64; j4 += 4) {
                float4 v = *(const float4*)&sm.Ss[r][j4];
                float p0 = (diag && (j4 + 0 > r)) ? 0.f : expf(v.x - mmax);
                float p1 = (diag && (j4 + 1 > r)) ? 0.f : expf(v.y - mmax);
                float p2 = (diag && (j4 + 2 > r)) ? 0.f : expf(v.z - mmax);
                float p3 = (diag && (j4 + 3 > r)) ? 0.f : expf(v.w - mmax);
                sm.Pt[j4 + 0][r] = p0;
                sm.Pt[j4 + 1][r] = p1;
                sm.Pt[j4 + 2][r] = p2;
                sm.Pt[j4 + 3][r] = p3;
                lsum += p0 + p1 + p2 + p3;
            }
            sm.mrow[r] = mmax;
            sm.lrow[r] = sm.lrow[r] * alpha + lsum;
            sm.arow[r] = alpha;
        }
        __syncthreads();

        // O = O*alpha + P @ V
        float a0 = sm.arow[ty], a1 = sm.arow[ty + 16];
        float a2 = sm.arow[ty + 32], a3 = sm.arow[ty + 48];
#pragma unroll
        for (int jj = 0; jj < 4; ++jj) {
            acc[0][jj] *= a0; acc[1][jj] *= a1;
            acc[2][jj] *= a2; acc[3][jj] *= a3;
        }
#pragma unroll 16
        for (int k = 0; k < 64; ++k) {
            float p0 = sm.Pt[k][ty],      p1 = sm.Pt[k][ty + 16];
            float p2 = sm.Pt[k][ty + 32], p3 = sm.Pt[k][ty + 48];
            float v0 = sm.Vs[k][tx],      v1 = sm.Vs[k][tx + 16];
            float v2 = sm.Vs[k][tx + 32], v3 = sm.Vs[k][tx + 48];
            acc[0][0] += p0 * v0; acc[0][1] += p0 * v1; acc[0][2] += p0 * v2; acc[0][3] += p0 * v3;
            acc[1][0] += p1 * v0; acc[1][1] += p1 * v1; acc[1][2] += p1 * v2; acc[1][3] += p1 * v3;
            acc[2][0] += p2 * v0; acc[2][1] += p2 * v1; acc[2][2] += p2 * v2; acc[2][3] += p2 * v3;
            acc[3][0] += p3 * v0; acc[3][1] += p3 * v1; acc[3][2] += p3 * v2; acc[3][3] += p3 * v3;
        }
    }

    // final normalize + store
    float inv[4];
    inv[0] = 1.f / sm.lrow[ty];      inv[1] = 1.f / sm.lrow[ty + 16];
    inv[2] = 1.f / sm.lrow[ty + 32]; inv[3] = 1.f / sm.lrow[ty + 48];
    float* zb = z + (size_t)(b * LSEQ + qb * 64) * EMB + h * 64;
#pragma unroll
    for (int ii = 0; ii < 4; ++ii) {
        int i = ty + 16 * ii;
#pragma unroll
        for (int jj = 0; jj < 4; ++jj)
            zb[(size_t)i * EMB + tx + 16 * jj] = acc[ii][jj] * inv[ii];
    }
}

// ---------------------------------------------------------------------------
// Launch
// ---------------------------------------------------------------------------
extern "C" void kernel_launch(void* const* d_in, const int* in_sizes, int n_in,
                              void* d_out, int out_size)
{
    const float* x    = (const float*)d_in[0];
    // d_in[1] = mask (causal tril) — handled analytically, unused
    const float* Wq   = (const float*)d_in[2];
    const float* bq   = (const float*)d_in[3];
    const float* Wk   = (const float*)d_in[4];
    const float* bk   = (const float*)d_in[5];
    const float* Wv   = (const float*)d_in[6];
    const float* bv   = (const float*)d_in[7];
    const float* Wo   = (const float*)d_in[8];
    const float* bo   = (const float*)d_in[9];
    const float* W1   = (const float*)d_in[10];
    const float* c1   = (const float*)d_in[11];
    const float* W2   = (const float*)d_in[12];
    const float* c2   = (const float*)d_in[13];
    const float* g1   = (const float*)d_in[14];
    const float* be1  = (const float*)d_in[15];
    const float* g2   = (const float*)d_in[16];
    const float* be2  = (const float*)d_in[17];
    float* out = (float*)d_out;

    float *wqkv, *bqkv, *qkv, *zz, *t1, *hh, *ff;
    cudaGetSymbolAddress((void**)&wqkv, g_wqkv);
    cudaGetSymbolAddress((void**)&bqkv, g_bqkv);
    cudaGetSymbolAddress((void**)&qkv,  g_qkv);
    cudaGetSymbolAddress((void**)&zz,   g_z);
    cudaGetSymbolAddress((void**)&t1,   g_t1);
    cudaGetSymbolAddress((void**)&hh,   g_h);
    cudaGetSymbolAddress((void**)&ff,   g_ff);

    cudaFuncSetAttribute(attn_kernel, cudaFuncAttributeMaxDynamicSharedMemorySize,
                         (int)sizeof(AttnSmem));

    // 1. pack QKV weights/biases
    pack_qkv_kernel<<<(EMB * N3E + 255) / 256, 256>>>(Wq, Wk, Wv, bq, bk, bv);

    // 2. QKV projection: qkv = x @ Wqkv + bqkv   (4096 x 3072, K=1024)
    sgemm128<false, false><<<dim3(N3E / 128, MR / 128), 256>>>(
        x, wqkv, bqkv, nullptr, qkv, MR, N3E, EMB);

    // 3. causal attention -> z
    attn_kernel<<<dim3(LSEQ / 64, HN, BSZ), 256, sizeof(AttnSmem)>>>(qkv, zz);

    // 4. t1 = z @ Wo + bo + x
    sgemm128<false, true><<<dim3(EMB / 128, MR / 128), 256>>>(
        zz, Wo, bo, x, t1, MR, EMB, EMB);

    // 5. h = LN1(t1)
    layernorm_kernel<<<MR, 256>>>(t1, g1, be1, hh);

    // 6. ff = relu(h @ W1 + c1)   (4096 x 4096, K=1024)
    sgemm128<true, false><<<dim3(DFF / 128, MR / 128), 256>>>(
        hh, W1, c1, nullptr, ff, MR, DFF, EMB);

    // 7. t1 = ff @ W2 + c2 + h   (4096 x 1024, K=4096)
    sgemm128<false, true><<<dim3(EMB / 128, MR / 128), 256>>>(
        ff, W2, c2, hh, t1, MR, EMB, DFF);

    // 8. out = LN2(t1)
    layernorm_kernel<<<MR, 256>>>(t1, g2, be2, out);
}